// round 1
// baseline (speedup 1.0000x reference)
#include <cuda_runtime.h>
#include <math.h>

#define BB 64
#define TT 512
#define HH 768
#define LL 32

// Scratch (static device globals: no allocation allowed)
__device__ float d_em[BB * TT * LL];   // emissions, 4 MB
__device__ float d_part[BB];           // per-batch (denom - numer)

// ---- packed f32x2 helpers (Blackwell FFMA2 path, PTX-only) ----
__device__ __forceinline__ unsigned long long pk2(float a, float b) {
    unsigned long long r;
    asm("mov.b64 %0, {%1, %2};" : "=l"(r) : "f"(a), "f"(b));
    return r;
}
__device__ __forceinline__ void upk2(unsigned long long v, float& a, float& b) {
    asm("mov.b64 {%0, %1}, %2;" : "=f"(a), "=f"(b) : "l"(v));
}
__device__ __forceinline__ unsigned long long f2fma(unsigned long long a,
                                                    unsigned long long b,
                                                    unsigned long long c) {
    unsigned long long d;
    asm("fma.rn.f32x2 %0, %1, %2, %3;" : "=l"(d) : "l"(a), "l"(b), "l"(c));
    return d;
}

// ============================================================
// Kernel 1: emissions = hidden_states @ W + b   (fp32, FFMA2)
// Tile: 32 rows x 32 cols per block, 256 threads.
// thread -> (r = tid>>3, jq = tid&7), 4 outputs j = jq*4..jq*4+3
// ============================================================
__global__ __launch_bounds__(256) void gemm_k(const float* __restrict__ hs,
                                              const float* __restrict__ W,
                                              const float* __restrict__ bias) {
    __shared__ float hsh[32][33];
    __shared__ float4 wsh[32][8];
    const int t = threadIdx.x;
    const int rowBase = blockIdx.x * 32;
    const int r = t >> 3, jq = t & 7;

    float4 bb = reinterpret_cast<const float4*>(bias)[jq];
    unsigned long long acc01 = pk2(bb.x, bb.y);
    unsigned long long acc23 = pk2(bb.z, bb.w);

    for (int k0 = 0; k0 < HH; k0 += 32) {
#pragma unroll
        for (int i = 0; i < 4; i++) {
            int idx = t + i * 256;
            hsh[idx >> 5][idx & 31] = hs[(rowBase + (idx >> 5)) * HH + k0 + (idx & 31)];
            reinterpret_cast<float*>(wsh)[idx] = W[k0 * LL + idx];
        }
        __syncthreads();
#pragma unroll
        for (int kk = 0; kk < 32; kk++) {
            float hv = hsh[r][kk];
            unsigned long long hv2 = pk2(hv, hv);
            ulonglong2 w2 = *reinterpret_cast<const ulonglong2*>(&wsh[kk][jq]);
            acc01 = f2fma(hv2, w2.x, acc01);
            acc23 = f2fma(hv2, w2.y, acc23);
        }
        __syncthreads();
    }
    float a0, a1, a2, a3;
    upk2(acc01, a0, a1);
    upk2(acc23, a2, a3);
    reinterpret_cast<float4*>(d_em)[(rowBase + r) * 8 + jq] = make_float4(a0, a1, a2, a3);
}

// ============================================================
// Kernel 2: CRF per batch. 1 block/batch, 3 warps:
//   warp0: forward logsumexp recursion -> denom
//   warp1: Viterbi recursion + hist (shared) -> best_last
//   warp2: numerator (gold path score)
// thread 0: backtrace from shared hist -> pred_labels
// ============================================================
__global__ __launch_bounds__(96) void crf_k(const int* __restrict__ attn,
                                            const int* __restrict__ labels,
                                            const float* __restrict__ startT,
                                            const float* __restrict__ endT,
                                            const float* __restrict__ trans,
                                            float* __restrict__ out) {
    __shared__ unsigned char hist[TT - 1][LL];
    __shared__ float sh_denom, sh_numer;
    __shared__ int sh_best;

    const int b = blockIdx.x;
    const int tid = threadIdx.x;
    const int w = tid >> 5, lane = tid & 31;
    const float* emb = d_em + b * TT * LL;

    // sequence length (mask is a prefix mask)
    int len = 0;
    {
        const int* am = attn + b * TT;
        for (int tt = lane; tt < TT; tt += 32) len += am[tt];
#pragma unroll
        for (int o = 16; o; o >>= 1) len += __shfl_xor_sync(0xffffffffu, len, o);
    }

    if (w == 0) {
        // -------- forward recursion (log partition) --------
        float Et[32];
#pragma unroll
        for (int i = 0; i < 32; i++) Et[i] = __expf(trans[i * LL + lane]);
        float score = startT[lane] + emb[lane];
        float e1 = emb[LL + lane];
        float e2 = emb[2 * LL + lane];
        for (int t = 1; t < TT; t++) {
            float emt = e1;
            e1 = e2;
            int tp = (t + 2 < TT) ? (t + 2) : (TT - 1);
            e2 = emb[tp * LL + lane];

            // logsumexp_i(score_i + tr_ij) = ref + log(sum_i exp(score_i-ref)*Et_i)
            float ref = __shfl_sync(0xffffffffu, score, 0);
            float p = __expf(score - ref);
            float s0 = 0.f, s1 = 0.f, s2 = 0.f, s3 = 0.f;
#pragma unroll
            for (int i = 0; i < 32; i += 4) {
                s0 = fmaf(__shfl_sync(0xffffffffu, p, i + 0), Et[i + 0], s0);
                s1 = fmaf(__shfl_sync(0xffffffffu, p, i + 1), Et[i + 1], s1);
                s2 = fmaf(__shfl_sync(0xffffffffu, p, i + 2), Et[i + 2], s2);
                s3 = fmaf(__shfl_sync(0xffffffffu, p, i + 3), Et[i + 3], s3);
            }
            float nxt = ref + __logf((s0 + s1) + (s2 + s3)) + emt;
            if (t < len) score = nxt;
        }
        // denom = logsumexp_j(score_j + end_j)
        float v = score + endT[lane];
        float ref = __shfl_sync(0xffffffffu, v, 0);
        float e = __expf(v - ref);
#pragma unroll
        for (int o = 16; o; o >>= 1) e += __shfl_xor_sync(0xffffffffu, e, o);
        if (lane == 0) sh_denom = ref + __logf(e);
    } else if (w == 1) {
        // -------- Viterbi recursion --------
        float tr[32];
#pragma unroll
        for (int i = 0; i < 32; i++) tr[i] = trans[i * LL + lane];
        float vs = startT[lane] + emb[lane];
        float e1 = emb[LL + lane];
        float e2 = emb[2 * LL + lane];
        for (int t = 1; t < TT; t++) {
            float emt = e1;
            e1 = e2;
            int tp = (t + 2 < TT) ? (t + 2) : (TT - 1);
            e2 = emb[tp * LL + lane];

            float bst0 = -3.0e38f, bst1 = -3.0e38f, bst2 = -3.0e38f, bst3 = -3.0e38f;
            int bi0 = 0, bi1 = 8, bi2 = 16, bi3 = 24;
#pragma unroll
            for (int u = 0; u < 8; u++) {
                float v0 = __shfl_sync(0xffffffffu, vs, u) + tr[u];
                float v1 = __shfl_sync(0xffffffffu, vs, 8 + u) + tr[8 + u];
                float v2 = __shfl_sync(0xffffffffu, vs, 16 + u) + tr[16 + u];
                float v3 = __shfl_sync(0xffffffffu, vs, 24 + u) + tr[24 + u];
                if (v0 > bst0) { bst0 = v0; bi0 = u; }
                if (v1 > bst1) { bst1 = v1; bi1 = 8 + u; }
                if (v2 > bst2) { bst2 = v2; bi2 = 16 + u; }
                if (v3 > bst3) { bst3 = v3; bi3 = 24 + u; }
            }
            // merge preferring lowest index on ties (argmax-first semantics)
            float best = bst0; int bi = bi0;
            if (bst1 > best) { best = bst1; bi = bi1; }
            if (bst2 > best) { best = bst2; bi = bi2; }
            if (bst3 > best) { best = bst3; bi = bi3; }
            hist[t - 1][lane] = (unsigned char)bi;
            if (t < len) vs = best + emt;
        }
        // best_last = argmax_j (vs_j + end_j), first index on ties
        float v = vs + endT[lane];
        int idx = lane;
#pragma unroll
        for (int o = 16; o; o >>= 1) {
            float ov = __shfl_xor_sync(0xffffffffu, v, o);
            int oi = __shfl_xor_sync(0xffffffffu, idx, o);
            if (ov > v || (ov == v && oi < idx)) { v = ov; idx = oi; }
        }
        if (lane == 0) sh_best = idx;
    } else {
        // -------- numerator (gold path score) --------
        const int* lab = labels + b * TT;
        float part = 0.f;
        for (int t = 1 + lane; t < TT; t += 32) {
            if (t < len) {
                int lt = lab[t], lp = lab[t - 1];
                part += emb[t * LL + lt] + trans[lp * LL + lt];
            }
        }
#pragma unroll
        for (int o = 16; o; o >>= 1) part += __shfl_xor_sync(0xffffffffu, part, o);
        if (lane == 0) {
            int l0 = lab[0];
            int llast = lab[len - 1];
            part += startT[l0] + emb[l0] + endT[llast];
            sh_numer = part;
        }
    }
    __syncthreads();

    if (tid == 0) {
        d_part[b] = sh_denom - sh_numer;
        // -------- backtrace (hist in shared) --------
        const int last_idx = len - 1;
        const int bestl = sh_best;
        float* pred = out + 1 + b * TT;
        pred[TT - 1] = (last_idx == TT - 1) ? (float)bestl : 0.0f;
        int carry = bestl;
        for (int t = TT - 2; t >= 0; t--) {
            int prev = hist[t][carry];
            float o;
            if (t == last_idx)      o = (float)bestl;
            else if (t > last_idx)  o = 0.0f;
            else                    o = (float)prev;
            pred[t] = o;
            carry = (t < last_idx) ? prev : bestl;
        }
    }
}

// ============================================================
// Kernel 3: deterministic loss reduce (no float atomics)
// ============================================================
__global__ void fin_k(float* __restrict__ out) {
    int l = threadIdx.x;
    float v = d_part[2 * l] + d_part[2 * l + 1];
#pragma unroll
    for (int o = 16; o; o >>= 1) v += __shfl_xor_sync(0xffffffffu, v, o);
    if (l == 0) out[0] = v;
}

extern "C" void kernel_launch(void* const* d_in, const int* in_sizes, int n_in,
                              void* d_out, int out_size) {
    (void)in_sizes; (void)n_in; (void)out_size;
    const float* hs     = (const float*)d_in[0];
    const int*   attn   = (const int*)d_in[1];
    const int*   labels = (const int*)d_in[2];
    const float* W      = (const float*)d_in[3];
    const float* bias   = (const float*)d_in[4];
    const float* startT = (const float*)d_in[5];
    const float* endT   = (const float*)d_in[6];
    const float* trans  = (const float*)d_in[7];
    float* out = (float*)d_out;

    gemm_k<<<(BB * TT) / 32, 256>>>(hs, W, bias);
    crf_k<<<BB, 96>>>(attn, labels, startT, endT, trans, out);
    fin_k<<<1, 32>>>(out);
}

// round 2
// speedup vs baseline: 1.1103x; 1.1103x over previous
#include <cuda_runtime.h>
#include <math.h>

#define BB 64
#define TT 512
#define HH 768
#define LL 32

// Scratch (static device globals: no allocation allowed)
__device__ float d_em[BB * TT * LL];    // emissions (log domain), 4 MB
__device__ float d_emx[BB * TT * LL];   // exp(emissions), 4 MB
__device__ float d_part[BB];            // per-batch (denom - numer)

// ---- packed f32x2 helpers (Blackwell FFMA2 path, PTX-only) ----
__device__ __forceinline__ unsigned long long pk2(float a, float b) {
    unsigned long long r;
    asm("mov.b64 %0, {%1, %2};" : "=l"(r) : "f"(a), "f"(b));
    return r;
}
__device__ __forceinline__ void upk2(unsigned long long v, float& a, float& b) {
    asm("mov.b64 {%0, %1}, %2;" : "=f"(a), "=f"(b) : "l"(v));
}
__device__ __forceinline__ unsigned long long f2fma(unsigned long long a,
                                                    unsigned long long b,
                                                    unsigned long long c) {
    unsigned long long d;
    asm("fma.rn.f32x2 %0, %1, %2, %3;" : "=l"(d) : "l"(a), "l"(b), "l"(c));
    return d;
}
__device__ __forceinline__ float frcp(float x) {
    float r;
    asm("rcp.approx.f32 %0, %1;" : "=f"(r) : "f"(x));
    return r;
}

// ============================================================
// Kernel 1: emissions = hidden_states @ W + b    (fp32, FFMA2)
// Block tile: 256 rows x 32 cols, 128 threads, thread tile 8x8.
// hsh stored transposed [k][row] so both operands are LDS.128.
// Epilogue writes em and exp(em).
// ============================================================
#define KC 16
__global__ __launch_bounds__(128) void gemm_k(const float* __restrict__ hs,
                                              const float* __restrict__ W,
                                              const float* __restrict__ bias) {
    __shared__ float hsh[KC][256];
    __shared__ float wsh[KC][32];
    const int tid = threadIdx.x;
    const int rowBase = blockIdx.x * 256;
    const int tr = tid >> 2, tc = tid & 3;
    const int r0 = tr * 8, c0 = tc * 8;

    unsigned long long acc[8][4];
    {
        float4 b0 = *reinterpret_cast<const float4*>(bias + c0);
        float4 b1 = *reinterpret_cast<const float4*>(bias + c0 + 4);
#pragma unroll
        for (int r = 0; r < 8; r++) {
            acc[r][0] = pk2(b0.x, b0.y);
            acc[r][1] = pk2(b0.z, b0.w);
            acc[r][2] = pk2(b1.x, b1.y);
            acc[r][3] = pk2(b1.z, b1.w);
        }
    }

    // register prefetch buffers
    float4 hld[8];
    float  wld[4];

    const int hrow = tid >> 2;            // rows for hs loads come from idx below
    (void)hrow;

    // load chunk 0
#pragma unroll
    for (int i = 0; i < 8; i++) {
        int idx = tid + i * 128;
        int row = idx >> 2, kq = idx & 3;
        hld[i] = *reinterpret_cast<const float4*>(hs + (size_t)(rowBase + row) * HH + kq * 4);
    }
#pragma unroll
    for (int i = 0; i < 4; i++) {
        int idx = tid + i * 128;
        wld[i] = W[(idx >> 5) * LL + (idx & 31)];
    }

    const int NCH = HH / KC;  // 48
    for (int ch = 0; ch < NCH; ch++) {
        __syncthreads();
        // store current chunk to shared
#pragma unroll
        for (int i = 0; i < 8; i++) {
            int idx = tid + i * 128;
            int row = idx >> 2, kq = idx & 3;
            hsh[kq * 4 + 0][row] = hld[i].x;
            hsh[kq * 4 + 1][row] = hld[i].y;
            hsh[kq * 4 + 2][row] = hld[i].z;
            hsh[kq * 4 + 3][row] = hld[i].w;
        }
#pragma unroll
        for (int i = 0; i < 4; i++) {
            int idx = tid + i * 128;
            wsh[idx >> 5][idx & 31] = wld[i];
        }
        __syncthreads();

        // prefetch next chunk
        if (ch + 1 < NCH) {
            int k0 = (ch + 1) * KC;
#pragma unroll
            for (int i = 0; i < 8; i++) {
                int idx = tid + i * 128;
                int row = idx >> 2, kq = idx & 3;
                hld[i] = *reinterpret_cast<const float4*>(hs + (size_t)(rowBase + row) * HH + k0 + kq * 4);
            }
#pragma unroll
            for (int i = 0; i < 4; i++) {
                int idx = tid + i * 128;
                wld[i] = W[(k0 + (idx >> 5)) * LL + (idx & 31)];
            }
        }

        // FMA over this chunk
#pragma unroll
        for (int kk = 0; kk < KC; kk++) {
            float4 h0 = *reinterpret_cast<const float4*>(&hsh[kk][r0]);
            float4 h1 = *reinterpret_cast<const float4*>(&hsh[kk][r0 + 4]);
            float4 w0 = *reinterpret_cast<const float4*>(&wsh[kk][c0]);
            float4 w1 = *reinterpret_cast<const float4*>(&wsh[kk][c0 + 4]);
            unsigned long long wp0 = pk2(w0.x, w0.y);
            unsigned long long wp1 = pk2(w0.z, w0.w);
            unsigned long long wp2 = pk2(w1.x, w1.y);
            unsigned long long wp3 = pk2(w1.z, w1.w);
            float hv[8] = {h0.x, h0.y, h0.z, h0.w, h1.x, h1.y, h1.z, h1.w};
#pragma unroll
            for (int r = 0; r < 8; r++) {
                unsigned long long hv2 = pk2(hv[r], hv[r]);
                acc[r][0] = f2fma(hv2, wp0, acc[r][0]);
                acc[r][1] = f2fma(hv2, wp1, acc[r][1]);
                acc[r][2] = f2fma(hv2, wp2, acc[r][2]);
                acc[r][3] = f2fma(hv2, wp3, acc[r][3]);
            }
        }
    }

    // epilogue: write em and exp(em)
#pragma unroll
    for (int r = 0; r < 8; r++) {
        float a[8];
        upk2(acc[r][0], a[0], a[1]);
        upk2(acc[r][1], a[2], a[3]);
        upk2(acc[r][2], a[4], a[5]);
        upk2(acc[r][3], a[6], a[7]);
        size_t base = (size_t)(rowBase + r0 + r) * LL + c0;
        *reinterpret_cast<float4*>(d_em + base)     = make_float4(a[0], a[1], a[2], a[3]);
        *reinterpret_cast<float4*>(d_em + base + 4) = make_float4(a[4], a[5], a[6], a[7]);
        *reinterpret_cast<float4*>(d_emx + base)     = make_float4(__expf(a[0]), __expf(a[1]), __expf(a[2]), __expf(a[3]));
        *reinterpret_cast<float4*>(d_emx + base + 4) = make_float4(__expf(a[4]), __expf(a[5]), __expf(a[6]), __expf(a[7]));
    }
}

// ============================================================
// Kernel 2: CRF per batch. 1 block/batch, 3 warps:
//   warp0: forward (linear-domain, periodic renorm) -> denom
//   warp1: Viterbi recursion + hist (shared) -> best_last
//   warp2: numerator (gold path score)
// thread 0: backtrace from shared hist -> pred_labels
// ============================================================
__global__ __launch_bounds__(96) void crf_k(const int* __restrict__ attn,
                                            const int* __restrict__ labels,
                                            const float* __restrict__ startT,
                                            const float* __restrict__ endT,
                                            const float* __restrict__ trans,
                                            float* __restrict__ out) {
    __shared__ unsigned char hist[TT - 1][LL];
    __shared__ float sh_denom, sh_numer;
    __shared__ int sh_best;

    const int b = blockIdx.x;
    const int tid = threadIdx.x;
    const int w = tid >> 5, lane = tid & 31;
    const float* emb = d_em + (size_t)b * TT * LL;
    const float* embx = d_emx + (size_t)b * TT * LL;

    // sequence length (mask is a prefix mask)
    int len = 0;
    {
        const int* am = attn + b * TT;
        for (int tt = lane; tt < TT; tt += 32) len += am[tt];
#pragma unroll
        for (int o = 16; o; o >>= 1) len += __shfl_xor_sync(0xffffffffu, len, o);
    }

    if (w == 0) {
        // -------- forward recursion, linear domain --------
        float Et[32];
#pragma unroll
        for (int i = 0; i < 32; i++) Et[i] = __expf(trans[i * LL + lane]);
        float sc0 = startT[lane] + emb[lane];
        float ref0 = __shfl_sync(0xffffffffu, sc0, 0);
        float u = __expf(sc0 - ref0);
        float c = ref0;

        float x1 = embx[LL + lane];
        float x2 = embx[2 * LL + lane];
        for (int t = 1; t < len; t++) {
            float ext = x1;
            x1 = x2;
            int tp = (t + 2 < TT) ? (t + 2) : (TT - 1);
            x2 = embx[tp * LL + lane];

            float s0 = 0.f, s1 = 0.f, s2 = 0.f, s3 = 0.f;
#pragma unroll
            for (int i = 0; i < 32; i += 4) {
                s0 = fmaf(__shfl_sync(0xffffffffu, u, i + 0), Et[i + 0], s0);
                s1 = fmaf(__shfl_sync(0xffffffffu, u, i + 1), Et[i + 1], s1);
                s2 = fmaf(__shfl_sync(0xffffffffu, u, i + 2), Et[i + 2], s2);
                s3 = fmaf(__shfl_sync(0xffffffffu, u, i + 3), Et[i + 3], s3);
            }
            u = ext * ((s0 + s1) + (s2 + s3));

            if ((t & 7) == 0) {
                float r = __shfl_sync(0xffffffffu, u, 0);
                u *= frcp(r);
                c += __logf(r);
            }
        }
        // denom = c + log(sum_j u_j * exp(end_j))
        float v = u * __expf(endT[lane]);
#pragma unroll
        for (int o = 16; o; o >>= 1) v += __shfl_xor_sync(0xffffffffu, v, o);
        if (lane == 0) sh_denom = c + __logf(v);
    } else if (w == 1) {
        // -------- Viterbi recursion --------
        float tr[32];
#pragma unroll
        for (int i = 0; i < 32; i++) tr[i] = trans[i * LL + lane];
        float vs = startT[lane] + emb[lane];
        float e1 = emb[LL + lane];
        float e2 = emb[2 * LL + lane];
        for (int t = 1; t < len; t++) {
            float emt = e1;
            e1 = e2;
            int tp = (t + 2 < TT) ? (t + 2) : (TT - 1);
            e2 = emb[tp * LL + lane];

            float bst0 = -3.0e38f, bst1 = -3.0e38f, bst2 = -3.0e38f, bst3 = -3.0e38f;
            int bi0 = 0, bi1 = 8, bi2 = 16, bi3 = 24;
#pragma unroll
            for (int u = 0; u < 8; u++) {
                float v0 = __shfl_sync(0xffffffffu, vs, u) + tr[u];
                float v1 = __shfl_sync(0xffffffffu, vs, 8 + u) + tr[8 + u];
                float v2 = __shfl_sync(0xffffffffu, vs, 16 + u) + tr[16 + u];
                float v3 = __shfl_sync(0xffffffffu, vs, 24 + u) + tr[24 + u];
                if (v0 > bst0) { bst0 = v0; bi0 = u; }
                if (v1 > bst1) { bst1 = v1; bi1 = 8 + u; }
                if (v2 > bst2) { bst2 = v2; bi2 = 16 + u; }
                if (v3 > bst3) { bst3 = v3; bi3 = 24 + u; }
            }
            // merge preferring lowest index on ties (argmax-first semantics)
            float best = bst0; int bi = bi0;
            if (bst1 > best) { best = bst1; bi = bi1; }
            if (bst2 > best) { best = bst2; bi = bi2; }
            if (bst3 > best) { best = bst3; bi = bi3; }
            hist[t - 1][lane] = (unsigned char)bi;
            vs = best + emt;
        }
        // best_last = argmax_j (vs_j + end_j), first index on ties
        float v = vs + endT[lane];
        int idx = lane;
#pragma unroll
        for (int o = 16; o; o >>= 1) {
            float ov = __shfl_xor_sync(0xffffffffu, v, o);
            int oi = __shfl_xor_sync(0xffffffffu, idx, o);
            if (ov > v || (ov == v && oi < idx)) { v = ov; idx = oi; }
        }
        if (lane == 0) sh_best = idx;
    } else {
        // -------- numerator (gold path score) --------
        const int* lab = labels + b * TT;
        float part = 0.f;
        for (int t = 1 + lane; t < TT; t += 32) {
            if (t < len) {
                int lt = lab[t], lp = lab[t - 1];
                part += emb[t * LL + lt] + trans[lp * LL + lt];
            }
        }
#pragma unroll
        for (int o = 16; o; o >>= 1) part += __shfl_xor_sync(0xffffffffu, part, o);
        if (lane == 0) {
            int l0 = lab[0];
            int llast = lab[len - 1];
            part += startT[l0] + emb[l0] + endT[llast];
            sh_numer = part;
        }
    }
    __syncthreads();

    if (tid == 0) {
        d_part[b] = sh_denom - sh_numer;
        // -------- backtrace (hist in shared) --------
        const int last_idx = len - 1;
        const int bestl = sh_best;
        float* pred = out + 1 + (size_t)b * TT;
        pred[TT - 1] = (last_idx == TT - 1) ? (float)bestl : 0.0f;
        int carry = bestl;
        for (int t = TT - 2; t >= 0; t--) {
            int prev = hist[t][carry];
            float o;
            if (t == last_idx)      o = (float)bestl;
            else if (t > last_idx)  o = 0.0f;
            else                    o = (float)prev;
            pred[t] = o;
            carry = (t < last_idx) ? prev : bestl;
        }
    }
}

// ============================================================
// Kernel 3: deterministic loss reduce (no float atomics)
// ============================================================
__global__ void fin_k(float* __restrict__ out) {
    int l = threadIdx.x;
    float v = d_part[2 * l] + d_part[2 * l + 1];
#pragma unroll
    for (int o = 16; o; o >>= 1) v += __shfl_xor_sync(0xffffffffu, v, o);
    if (l == 0) out[0] = v;
}

extern "C" void kernel_launch(void* const* d_in, const int* in_sizes, int n_in,
                              void* d_out, int out_size) {
    (void)in_sizes; (void)n_in; (void)out_size;
    const float* hs     = (const float*)d_in[0];
    const int*   attn   = (const int*)d_in[1];
    const int*   labels = (const int*)d_in[2];
    const float* W      = (const float*)d_in[3];
    const float* bias   = (const float*)d_in[4];
    const float* startT = (const float*)d_in[5];
    const float* endT   = (const float*)d_in[6];
    const float* trans  = (const float*)d_in[7];
    float* out = (float*)d_out;

    gemm_k<<<(BB * TT) / 256, 128>>>(hs, W, bias);
    crf_k<<<BB, 96>>>(attn, labels, startT, endT, trans, out);
    fin_k<<<1, 32>>>(out);
}